// round 4
// baseline (speedup 1.0000x reference)
#include <cuda_runtime.h>
#include <cuda_bf16.h>
#include <cstdint>

#define N_NODES 8192
#define FIN     512
#define FOUT    256
#define NSPLIT  2
#define KHALF   (N_NODES / NSPLIT)   // 4096
#define BKC     64                   // K-chunk (64 j per mainloop iter)
#define NCHUNK  (KHALF / BKC)        // 64
#define NWORDS  (N_NODES / 32)       // 256 mask words per row

// ---------------------------------------------------------------------------
// Device scratch
// ---------------------------------------------------------------------------
__device__ float g_h[(size_t)N_NODES * FOUT];              // 8 MB   h = x@W
__device__ float g_s[2 * N_NODES];                         // s_src | s_dst
__device__ __nv_bfloat16 g_hT_hi[(size_t)FOUT * N_NODES];  // 4 MB
__device__ __nv_bfloat16 g_hT_lo[(size_t)FOUT * N_NODES];  // 4 MB
__device__ uint32_t g_maskT[(size_t)NWORDS * N_NODES];     // 8 MB   maskT[jw][i]
__device__ float g_pnum[(size_t)NSPLIT * N_NODES * FOUT];  // 16 MB
__device__ float g_pden[NSPLIT * N_NODES];

// mish(u) = u*(t^2+2t)/(t^2+2t+2), t=e^u
__device__ __forceinline__ float fast_mish(float u) {
    if (u > 30.f) return u;
    float t = __expf(u);
    float v = t * (t + 2.f);
    return u * __fdividef(v, v + 2.f);
}
__device__ __forceinline__ uint32_t smem_u32(const void* p) {
    uint32_t a;
    asm("{ .reg .u64 t; cvta.to.shared.u64 t, %1; cvt.u32.u64 %0, t; }" : "=r"(a) : "l"(p));
    return a;
}
__device__ __forceinline__ uint32_t pack_bf16(float a, float b) {
    return (uint32_t)__bfloat16_as_ushort(__float2bfloat16(a)) |
           ((uint32_t)__bfloat16_as_ushort(__float2bfloat16(b)) << 16);
}
#define SW128(x) ((x) ^ (((x) >> 3) & 0x70))

// ---- baseline-PTX tensor / async ops (compute_103-safe) --------------------
__device__ __forceinline__ void ldsm4(uint32_t* r, uint32_t addr) {
    asm volatile("ldmatrix.sync.aligned.m8n8.x4.shared.b16 {%0,%1,%2,%3}, [%4];"
                 : "=r"(r[0]), "=r"(r[1]), "=r"(r[2]), "=r"(r[3]) : "r"(addr));
}
__device__ __forceinline__ void mma_bf16(float* d, const uint32_t* a,
                                         uint32_t b0, uint32_t b1) {
    asm volatile("mma.sync.aligned.m16n8k16.row.col.f32.bf16.bf16.f32 "
                 "{%0,%1,%2,%3}, {%4,%5,%6,%7}, {%8,%9}, {%0,%1,%2,%3};"
                 : "+f"(d[0]), "+f"(d[1]), "+f"(d[2]), "+f"(d[3])
                 : "r"(a[0]), "r"(a[1]), "r"(a[2]), "r"(a[3]), "r"(b0), "r"(b1));
}
__device__ __forceinline__ void cpa16(uint32_t s, const void* g) {
    asm volatile("cp.async.cg.shared.global [%0], [%1], 16;" :: "r"(s), "l"(g));
}
#define CPA_COMMIT() asm volatile("cp.async.commit_group;" ::: "memory")
#define CPA_WAIT0()  asm volatile("cp.async.wait_group 0;" ::: "memory")

#define MBAR_INIT(addr, cnt) \
    asm volatile("mbarrier.init.shared.b64 [%0], %1;" :: "r"(addr), "r"(cnt) : "memory")
#define MBAR_ARRIVE(addr) \
    asm volatile("mbarrier.arrive.shared.b64 _, [%0];" :: "r"(addr) : "memory")
__device__ __forceinline__ void mbar_wait(uint32_t mbar, uint32_t parity) {
    uint32_t done;
    asm volatile("{\n\t.reg .pred p;\n\t"
                 "mbarrier.try_wait.parity.shared.b64 p, [%1], %2;\n\t"
                 "selp.b32 %0, 1, 0, p;\n\t}" : "=r"(done) : "r"(mbar), "r"(parity) : "memory");
    if (!done) {
        asm volatile("{\n\t.reg .pred P1;\n\t"
                     "WL_%=:\n\t"
                     "mbarrier.try_wait.parity.shared.b64 P1, [%0], %1;\n\t"
                     "@P1 bra.uni WD_%=;\n\t"
                     "bra.uni WL_%=;\n\t"
                     "WD_%=:\n\t}" :: "r"(mbar), "r"(parity) : "memory");
    }
}

// ---------------------------------------------------------------------------
// Kernel 1: h = x @ W  (FFMA SGEMM)
// ---------------------------------------------------------------------------
__global__ __launch_bounds__(256) void k_sgemm_xw(
    const float* __restrict__ X, const float* __restrict__ W)
{
    __shared__ float As[16][64];
    __shared__ float Bs[16][64];
    const int bn = blockIdx.x * 64, bm = blockIdx.y * 64;
    const int tid = threadIdx.x, tx = tid & 15, ty = tid >> 4;
    float acc[4][4];
#pragma unroll
    for (int r = 0; r < 4; r++)
#pragma unroll
        for (int c = 0; c < 4; c++) acc[r][c] = 0.f;
    for (int k0 = 0; k0 < FIN; k0 += 16) {
#pragma unroll
        for (int i = tid; i < 1024; i += 256) {
            int m = i >> 4, k = i & 15;
            As[k][m] = X[(size_t)(bm + m) * FIN + k0 + k];
        }
#pragma unroll
        for (int i = tid; i < 1024; i += 256) {
            int k = i >> 6, n = i & 63;
            Bs[k][n] = W[(size_t)(k0 + k) * FOUT + bn + n];
        }
        __syncthreads();
#pragma unroll
        for (int k = 0; k < 16; k++) {
            float4 a4 = *(const float4*)&As[k][ty * 4];
            float4 b4 = *(const float4*)&Bs[k][tx * 4];
            float a[4] = {a4.x, a4.y, a4.z, a4.w};
            float b[4] = {b4.x, b4.y, b4.z, b4.w};
#pragma unroll
            for (int r = 0; r < 4; r++)
#pragma unroll
                for (int c = 0; c < 4; c++) acc[r][c] = fmaf(a[r], b[c], acc[r][c]);
        }
        __syncthreads();
    }
#pragma unroll
    for (int r = 0; r < 4; r++) {
        float4 o = {acc[r][0], acc[r][1], acc[r][2], acc[r][3]};
        *(float4*)&g_h[(size_t)(bm + ty * 4 + r) * FOUT + bn + tx * 4] = o;
    }
}

// ---------------------------------------------------------------------------
// Kernel 2: s_src / s_dst
// ---------------------------------------------------------------------------
__global__ __launch_bounds__(256) void k_scores(const float* __restrict__ A)
{
    const int row = blockIdx.x * 8 + (threadIdx.x >> 5);
    const int lane = threadIdx.x & 31;
    const float4* h4 = (const float4*)(g_h + (size_t)row * FOUT);
    const float4* a14 = (const float4*)A;
    const float4* a24 = (const float4*)(A + FOUT);
    float s1 = 0.f, s2 = 0.f;
#pragma unroll
    for (int i = 0; i < 2; i++) {
        int idx = lane + i * 32;
        float4 h = h4[idx], a1 = a14[idx], a2 = a24[idx];
        s1 += h.x * a1.x + h.y * a1.y + h.z * a1.z + h.w * a1.w;
        s2 += h.x * a2.x + h.y * a2.y + h.z * a2.z + h.w * a2.w;
    }
#pragma unroll
    for (int off = 16; off; off >>= 1) {
        s1 += __shfl_down_sync(0xffffffffu, s1, off);
        s2 += __shfl_down_sync(0xffffffffu, s2, off);
    }
    if (lane == 0) { g_s[row] = s1; g_s[N_NODES + row] = s2; }
}

// ---------------------------------------------------------------------------
// Kernel 3: h -> h^T split bf16 hi + lo
// ---------------------------------------------------------------------------
__global__ __launch_bounds__(256) void k_hsplit()
{
    __shared__ float t[32][33];
    const int tid = threadIdx.x, tx = tid & 31, ty = tid >> 5;
    const int ibase = blockIdx.x * 32, nbase = blockIdx.y * 32;
#pragma unroll
    for (int r = 0; r < 4; r++)
        t[ty + r * 8][tx] = g_h[(size_t)(ibase + ty + r * 8) * FOUT + nbase + tx];
    __syncthreads();
#pragma unroll
    for (int r = 0; r < 4; r++) {
        int nl = ty + r * 8;
        float v = t[tx][nl];
        __nv_bfloat16 hi = __float2bfloat16(v);
        __nv_bfloat16 lo = __float2bfloat16(v - __bfloat162float(hi));
        size_t o = (size_t)(nbase + nl) * N_NODES + ibase + tx;
        g_hT_hi[o] = hi;
        g_hT_lo[o] = lo;
    }
}

// ---------------------------------------------------------------------------
// Kernel 3b: adj -> transposed bitmask  maskT[jw][i]
// CTA: 32 rows x 256 j (8 jwords). grid (N/32, N/256).
// ---------------------------------------------------------------------------
__global__ __launch_bounds__(256) void k_mask(const int* __restrict__ adj)
{
    __shared__ uint32_t sm[8][32];
    const int tid = threadIdx.x, lane = tid & 31, wid = tid >> 5;
    const int ibase = blockIdx.x * 32;
    const int jbase = blockIdx.y * 256;
#pragma unroll
    for (int rr = 0; rr < 4; rr++) {
        int il = wid * 4 + rr;
        const int* arow = adj + (size_t)(ibase + il) * N_NODES + jbase;
#pragma unroll
        for (int t = 0; t < 8; t++) {
            int av = arow[t * 32 + lane];
            uint32_t b = __ballot_sync(0xffffffffu, av > 0);
            if (lane == 0) sm[t][il] = b;
        }
    }
    __syncthreads();
    const int t = tid >> 5, il = tid & 31;
    g_maskT[(size_t)(jbase / 32 + t) * N_NODES + ibase + il] = sm[t][il];
}

// ---------------------------------------------------------------------------
// Kernel 4: warp-specialized attention.
// 320 threads: warps 0-7 consumers (MMA), warps 8-9 producers (w-gen + B loads).
// Grid (64, NSPLIT). CTA: M=128, N=256, K=4096.
// Stage layout (96KB x 2): A_hi 16K | A_lo 16K | B_hi 32K | B_lo 32K
// ---------------------------------------------------------------------------
#define ST_SZ 98304
#define ATTN_SMEM (2 * ST_SZ)   // 196608

__global__ __launch_bounds__(320, 1) void k_gat_attn_mma()
{
    extern __shared__ char smem[];
    __shared__ uint64_t bar_full[2], bar_empty[2];
    const uint32_t sb = smem_u32(smem);
    const int tid = threadIdx.x;
    const int lane = tid & 31;
    const int wid = tid >> 5;

    const int row0 = blockIdx.x * 128;
    const int half = blockIdx.y;
    const int jbase = half * KHALF;

    const uint32_t bf0 = smem_u32(&bar_full[0]),  bf1 = smem_u32(&bar_full[1]);
    const uint32_t be0 = smem_u32(&bar_empty[0]), be1 = smem_u32(&bar_empty[1]);
    if (tid == 0) {
        MBAR_INIT(bf0, 64u);  MBAR_INIT(bf1, 64u);
        MBAR_INIT(be0, 256u); MBAR_INIT(be1, 256u);
    }
    __syncthreads();

    if (tid < 256) {
        // ===================== CONSUMERS (8 warps, MMA) =====================
        const int warp_m = wid & 1;
        const int warp_n = wid >> 1;
        const uint32_t arow_base = (uint32_t)(warp_m * 64 + (lane & 15)) * 128;
        const int ksw = lane & 7;
        const int alsel = lane >> 4;

        float acc[4][8][4];
#pragma unroll
        for (int mt = 0; mt < 4; mt++)
#pragma unroll
            for (int nt = 0; nt < 8; nt++)
#pragma unroll
                for (int q = 0; q < 4; q++) acc[mt][nt][q] = 0.f;

        uint32_t pf0 = 0, pf1 = 0;
        for (int c = 0; c < NCHUNK; c++) {
            const int st = c & 1;
            if (st == 0) { mbar_wait(bf0, pf0); pf0 ^= 1; }
            else         { mbar_wait(bf1, pf1); pf1 ^= 1; }
            const uint32_t sbase = sb + st * ST_SZ;

#pragma unroll
            for (int ks = 0; ks < 4; ks++) {
                uint32_t Ah[4][4], Al[4][4];
                const int kcA = ks * 2 + alsel;
#pragma unroll
                for (int mt = 0; mt < 4; mt++) {
                    uint32_t addr = sbase + arow_base + mt * 2048 +
                                    (uint32_t)((kcA ^ ksw) << 4);
                    ldsm4(Ah[mt], addr);
                    ldsm4(Al[mt], addr + 16384);
                }
#pragma unroll
                for (int ng = 0; ng < 4; ng++) {
                    const int g = lane >> 3;
                    const int brow = warp_n * 64 + ng * 16 + (lane & 7) + ((g & 2) << 2);
                    const int kcB = ks * 2 + (g & 1);
                    uint32_t baddr = sbase + 32768 + (uint32_t)brow * 128 +
                                     (uint32_t)((kcB ^ ksw) << 4);
                    uint32_t Bh[4], Bl[4];
                    ldsm4(Bh, baddr);
                    ldsm4(Bl, baddr + 32768);
#pragma unroll
                    for (int mt = 0; mt < 4; mt++) {
                        mma_bf16(acc[mt][ng * 2],     Ah[mt], Bh[0], Bh[1]);
                        mma_bf16(acc[mt][ng * 2 + 1], Ah[mt], Bh[2], Bh[3]);
                        mma_bf16(acc[mt][ng * 2],     Ah[mt], Bl[0], Bl[1]);
                        mma_bf16(acc[mt][ng * 2 + 1], Ah[mt], Bl[2], Bl[3]);
                        mma_bf16(acc[mt][ng * 2],     Al[mt], Bh[0], Bh[1]);
                        mma_bf16(acc[mt][ng * 2 + 1], Al[mt], Bh[2], Bh[3]);
                    }
                }
            }
            if (st == 0) MBAR_ARRIVE(be0);
            else         MBAR_ARRIVE(be1);
        }

        // epilogue: numerators
        float* base = g_pnum + (size_t)half * N_NODES * FOUT;
#pragma unroll
        for (int mt = 0; mt < 4; mt++) {
#pragma unroll
            for (int nt = 0; nt < 8; nt++) {
                int row = row0 + warp_m * 64 + mt * 16 + (lane >> 2);
                int col = warp_n * 64 + nt * 8 + (lane & 3) * 2;
                float2 v0 = {acc[mt][nt][0], acc[mt][nt][1]};
                float2 v1 = {acc[mt][nt][2], acc[mt][nt][3]};
                *(float2*)&base[(size_t)row * FOUT + col] = v0;
                *(float2*)&base[(size_t)(row + 8) * FOUT + col] = v1;
            }
        }
    } else {
        // ===================== PRODUCERS (2 warps) ==========================
        const int p = tid - 256;                 // 0..63
        const float ssrc0 = g_s[row0 + p];
        const float ssrc1 = g_s[row0 + p + 64];
        const float* __restrict__ sdst = g_s + N_NODES;
        const char* __restrict__ hhi = (const char*)g_hT_hi;
        const char* __restrict__ hlo = (const char*)g_hT_lo;
        float psum0 = 0.f, psum1 = 0.f;

        uint32_t pe0 = 1, pe1 = 1;
        for (int c = 0; c < NCHUNK; c++) {
            const int st = c & 1;
            if (st == 0) { mbar_wait(be0, pe0); pe0 ^= 1; }
            else         { mbar_wait(be1, pe1); pe1 ^= 1; }
            const uint32_t sbase = sb + st * ST_SZ;
            const int j0 = jbase + c * BKC;

            // B tiles via cp.async: rows n = 4p..4p+3, 128B hi + 128B lo each
#pragma unroll
            for (int rr = 0; rr < 4; rr++) {
                const int n = p * 4 + rr;
                const size_t go = ((size_t)n * N_NODES + j0) * 2;
                const uint32_t db = (uint32_t)n * 128;
#pragma unroll
                for (int t = 0; t < 8; t++) {
                    uint32_t so = SW128(db + t * 16);
                    cpa16(sbase + 32768 + so, hhi + go + t * 16);
                    cpa16(sbase + 65536 + so, hlo + go + t * 16);
                }
            }
            CPA_COMMIT();

            // A tile: this lane owns rows p and p+64 (all 64 j)
            const int jw = j0 >> 5;
#pragma unroll
            for (int rl = 0; rl < 2; rl++) {
                const int r = p + rl * 64;
                const float ss = rl ? ssrc1 : ssrc0;
                const uint32_t m0 = g_maskT[(size_t)jw * N_NODES + row0 + r];
                const uint32_t m1 = g_maskT[(size_t)(jw + 1) * N_NODES + row0 + r];
                float ps = 0.f;
#pragma unroll
                for (int q = 0; q < 16; q++) {
                    const uint32_t m = (q < 8) ? m0 : m1;
                    const int shb = (q * 4) & 31;
                    float4 sv = __ldg((const float4*)(sdst + j0) + q);
                    float w0 = ((m >> (shb + 0)) & 1) ? __expf(fast_mish(ss + sv.x)) : 0.f;
                    float w1 = ((m >> (shb + 1)) & 1) ? __expf(fast_mish(ss + sv.y)) : 0.f;
                    float w2 = ((m >> (shb + 2)) & 1) ? __expf(fast_mish(ss + sv.z)) : 0.f;
                    float w3 = ((m >> (shb + 3)) & 1) ? __expf(fast_mish(ss + sv.w)) : 0.f;
                    ps += (w0 + w1) + (w2 + w3);
                    uint32_t h01 = pack_bf16(w0, w1), h23 = pack_bf16(w2, w3);
                    float r0 = w0 - __bfloat162float(__float2bfloat16(w0));
                    float r1 = w1 - __bfloat162float(__float2bfloat16(w1));
                    float r2 = w2 - __bfloat162float(__float2bfloat16(w2));
                    float r3 = w3 - __bfloat162float(__float2bfloat16(w3));
                    uint32_t l01 = pack_bf16(r0, r1), l23 = pack_bf16(r2, r3);
                    uint32_t bo = SW128((uint32_t)r * 128 + q * 8);
                    *(uint64_t*)(smem + st * ST_SZ + bo) =
                        (uint64_t)h01 | ((uint64_t)h23 << 32);
                    *(uint64_t*)(smem + st * ST_SZ + 16384 + bo) =
                        (uint64_t)l01 | ((uint64_t)l23 << 32);
                }
                if (rl == 0) psum0 += ps; else psum1 += ps;
            }

            CPA_WAIT0();
            if (st == 0) MBAR_ARRIVE(bf0);
            else         MBAR_ARRIVE(bf1);
        }
        // denominators: each lane owns its 2 rows completely for this half
        g_pden[half * N_NODES + row0 + p]      = psum0;
        g_pden[half * N_NODES + row0 + p + 64] = psum1;
    }
}

// ---------------------------------------------------------------------------
// Kernel 5: combine K-split partials + final mish
// ---------------------------------------------------------------------------
__global__ __launch_bounds__(256) void k_combine(float* __restrict__ out)
{
    const int idx = blockIdx.x * 256 + threadIdx.x;
    const int row = idx >> 6;
    const float4* p0 = (const float4*)g_pnum;
    const float4* p1 = (const float4*)(g_pnum + (size_t)N_NODES * FOUT);
    float inv = __fdividef(1.f, g_pden[row] + g_pden[N_NODES + row]);
    float4 a = p0[idx], b = p1[idx];
    float4 o;
    o.x = fast_mish((a.x + b.x) * inv);
    o.y = fast_mish((a.y + b.y) * inv);
    o.z = fast_mish((a.z + b.z) * inv);
    o.w = fast_mish((a.w + b.w) * inv);
    ((float4*)out)[idx] = o;
}

// ---------------------------------------------------------------------------
extern "C" void kernel_launch(void* const* d_in, const int* in_sizes, int n_in,
                              void* d_out, int out_size)
{
    const float* x   = (const float*)d_in[0];   // [8192, 512]
    const int*   adj = (const int*)  d_in[1];   // [8192, 8192]
    const float* w   = (const float*)d_in[2];   // [512, 256]
    const float* a   = (const float*)d_in[3];   // [512, 1]
    float* out = (float*)d_out;                 // [8192, 256]

    cudaFuncSetAttribute(k_gat_attn_mma, cudaFuncAttributeMaxDynamicSharedMemorySize,
                         ATTN_SMEM);

    k_mask<<<dim3(N_NODES / 32, N_NODES / 256), 256>>>(adj);
    k_sgemm_xw<<<dim3(FOUT / 64, N_NODES / 64), 256>>>(x, w);
    k_scores<<<N_NODES / 8, 256>>>(a);
    k_hsplit<<<dim3(N_NODES / 32, FOUT / 32), 256>>>();
    k_gat_attn_mma<<<dim3(N_NODES / 128, NSPLIT), 320, ATTN_SMEM>>>();
    k_combine<<<(N_NODES * FOUT / 4) / 256, 256>>>(out);
}

// round 5
// speedup vs baseline: 1.8960x; 1.8960x over previous
#include <cuda_runtime.h>
#include <cuda_bf16.h>
#include <cstdint>

#define N_NODES 8192
#define FIN     512
#define FOUT    256
#define NSPLIT  2
#define KHALF   (N_NODES / NSPLIT)   // 4096
#define BKC     64                   // K-chunk (64 j per mainloop iter)
#define NCHUNK  (KHALF / BKC)        // 64
#define NWORDS  (N_NODES / 32)       // 256 mask words per row

// ---------------------------------------------------------------------------
// Device scratch
// ---------------------------------------------------------------------------
__device__ float g_h[(size_t)N_NODES * FOUT];              // 8 MB   h = x@W
__device__ float g_s[2 * N_NODES];                         // s_src | s_dst
__device__ __nv_bfloat16 g_hT_hi[(size_t)FOUT * N_NODES];  // 4 MB
__device__ __nv_bfloat16 g_hT_lo[(size_t)FOUT * N_NODES];  // 4 MB
__device__ uint32_t g_maskT[(size_t)NWORDS * N_NODES];     // 8 MB   maskT[jw][i]
__device__ float g_pnum[(size_t)NSPLIT * N_NODES * FOUT];  // 16 MB
__device__ float g_pden[NSPLIT * N_NODES];

// mish(u) = u*(t^2+2t)/(t^2+2t+2), t=e^u
__device__ __forceinline__ float fast_mish(float u) {
    if (u > 30.f) return u;
    float t = __expf(u);
    float v = t * (t + 2.f);
    return u * __fdividef(v, v + 2.f);
}
__device__ __forceinline__ uint32_t smem_u32(const void* p) {
    uint32_t a;
    asm("{ .reg .u64 t; cvta.to.shared.u64 t, %1; cvt.u32.u64 %0, t; }" : "=r"(a) : "l"(p));
    return a;
}
__device__ __forceinline__ uint32_t pack_bf16(float a, float b) {
    return (uint32_t)__bfloat16_as_ushort(__float2bfloat16(a)) |
           ((uint32_t)__bfloat16_as_ushort(__float2bfloat16(b)) << 16);
}
#define SW128(x) ((x) ^ (((x) >> 3) & 0x70))

// ---- baseline-PTX tensor / async ops (compute_103-safe) --------------------
__device__ __forceinline__ void ldsm4(uint32_t* r, uint32_t addr) {
    asm volatile("ldmatrix.sync.aligned.m8n8.x4.shared.b16 {%0,%1,%2,%3}, [%4];"
                 : "=r"(r[0]), "=r"(r[1]), "=r"(r[2]), "=r"(r[3]) : "r"(addr));
}
__device__ __forceinline__ void mma_bf16(float* d, const uint32_t* a,
                                         uint32_t b0, uint32_t b1) {
    asm volatile("mma.sync.aligned.m16n8k16.row.col.f32.bf16.bf16.f32 "
                 "{%0,%1,%2,%3}, {%4,%5,%6,%7}, {%8,%9}, {%0,%1,%2,%3};"
                 : "+f"(d[0]), "+f"(d[1]), "+f"(d[2]), "+f"(d[3])
                 : "r"(a[0]), "r"(a[1]), "r"(a[2]), "r"(a[3]), "r"(b0), "r"(b1));
}
__device__ __forceinline__ void cpa16(uint32_t s, const void* g) {
    asm volatile("cp.async.cg.shared.global [%0], [%1], 16;" :: "r"(s), "l"(g));
}
#define CPA_COMMIT() asm volatile("cp.async.commit_group;" ::: "memory")
#define CPA_WAIT0()  asm volatile("cp.async.wait_group 0;" ::: "memory")

// ---------------------------------------------------------------------------
// Kernel 1: h = x @ W  (FFMA SGEMM)
// ---------------------------------------------------------------------------
__global__ __launch_bounds__(256) void k_sgemm_xw(
    const float* __restrict__ X, const float* __restrict__ W)
{
    __shared__ float As[16][64];
    __shared__ float Bs[16][64];
    const int bn = blockIdx.x * 64, bm = blockIdx.y * 64;
    const int tid = threadIdx.x, tx = tid & 15, ty = tid >> 4;
    float acc[4][4];
#pragma unroll
    for (int r = 0; r < 4; r++)
#pragma unroll
        for (int c = 0; c < 4; c++) acc[r][c] = 0.f;
    for (int k0 = 0; k0 < FIN; k0 += 16) {
#pragma unroll
        for (int i = tid; i < 1024; i += 256) {
            int m = i >> 4, k = i & 15;
            As[k][m] = X[(size_t)(bm + m) * FIN + k0 + k];
        }
#pragma unroll
        for (int i = tid; i < 1024; i += 256) {
            int k = i >> 6, n = i & 63;
            Bs[k][n] = W[(size_t)(k0 + k) * FOUT + bn + n];
        }
        __syncthreads();
#pragma unroll
        for (int k = 0; k < 16; k++) {
            float4 a4 = *(const float4*)&As[k][ty * 4];
            float4 b4 = *(const float4*)&Bs[k][tx * 4];
            float a[4] = {a4.x, a4.y, a4.z, a4.w};
            float b[4] = {b4.x, b4.y, b4.z, b4.w};
#pragma unroll
            for (int r = 0; r < 4; r++)
#pragma unroll
                for (int c = 0; c < 4; c++) acc[r][c] = fmaf(a[r], b[c], acc[r][c]);
        }
        __syncthreads();
    }
#pragma unroll
    for (int r = 0; r < 4; r++) {
        float4 o = {acc[r][0], acc[r][1], acc[r][2], acc[r][3]};
        *(float4*)&g_h[(size_t)(bm + ty * 4 + r) * FOUT + bn + tx * 4] = o;
    }
}

// ---------------------------------------------------------------------------
// Kernel 2: s_src / s_dst
// ---------------------------------------------------------------------------
__global__ __launch_bounds__(256) void k_scores(const float* __restrict__ A)
{
    const int row = blockIdx.x * 8 + (threadIdx.x >> 5);
    const int lane = threadIdx.x & 31;
    const float4* h4 = (const float4*)(g_h + (size_t)row * FOUT);
    const float4* a14 = (const float4*)A;
    const float4* a24 = (const float4*)(A + FOUT);
    float s1 = 0.f, s2 = 0.f;
#pragma unroll
    for (int i = 0; i < 2; i++) {
        int idx = lane + i * 32;
        float4 h = h4[idx], a1 = a14[idx], a2 = a24[idx];
        s1 += h.x * a1.x + h.y * a1.y + h.z * a1.z + h.w * a1.w;
        s2 += h.x * a2.x + h.y * a2.y + h.z * a2.z + h.w * a2.w;
    }
#pragma unroll
    for (int off = 16; off; off >>= 1) {
        s1 += __shfl_down_sync(0xffffffffu, s1, off);
        s2 += __shfl_down_sync(0xffffffffu, s2, off);
    }
    if (lane == 0) { g_s[row] = s1; g_s[N_NODES + row] = s2; }
}

// ---------------------------------------------------------------------------
// Kernel 3: h -> h^T split bf16 hi + lo
// ---------------------------------------------------------------------------
__global__ __launch_bounds__(256) void k_hsplit()
{
    __shared__ float t[32][33];
    const int tid = threadIdx.x, tx = tid & 31, ty = tid >> 5;
    const int ibase = blockIdx.x * 32, nbase = blockIdx.y * 32;
#pragma unroll
    for (int r = 0; r < 4; r++)
        t[ty + r * 8][tx] = g_h[(size_t)(ibase + ty + r * 8) * FOUT + nbase + tx];
    __syncthreads();
#pragma unroll
    for (int r = 0; r < 4; r++) {
        int nl = ty + r * 8;
        float v = t[tx][nl];
        __nv_bfloat16 hi = __float2bfloat16(v);
        __nv_bfloat16 lo = __float2bfloat16(v - __bfloat162float(hi));
        size_t o = (size_t)(nbase + nl) * N_NODES + ibase + tx;
        g_hT_hi[o] = hi;
        g_hT_lo[o] = lo;
    }
}

// ---------------------------------------------------------------------------
// Kernel 3b: adj -> transposed bitmask  maskT[jw][i]
// ---------------------------------------------------------------------------
__global__ __launch_bounds__(256) void k_mask(const int* __restrict__ adj)
{
    __shared__ uint32_t sm[8][32];
    const int tid = threadIdx.x, lane = tid & 31, wid = tid >> 5;
    const int ibase = blockIdx.x * 32;
    const int jbase = blockIdx.y * 256;
#pragma unroll
    for (int rr = 0; rr < 4; rr++) {
        int il = wid * 4 + rr;
        const int* arow = adj + (size_t)(ibase + il) * N_NODES + jbase;
#pragma unroll
        for (int t = 0; t < 8; t++) {
            int av = arow[t * 32 + lane];
            uint32_t b = __ballot_sync(0xffffffffu, av > 0);
            if (lane == 0) sm[t][il] = b;
        }
    }
    __syncthreads();
    const int t = tid >> 5, il = tid & 31;
    g_maskT[(size_t)(jbase / 32 + t) * N_NODES + ibase + il] = sm[t][il];
}

// ---------------------------------------------------------------------------
// Kernel 4: uniform-thread pipelined attention.
// 256 threads. Iteration c: consume stage c&1 (HMMA) interleaved with
// produce stage (c+1)&1 (MUFU w-gen + cp.async B). ONE syncthreads per iter.
// Grid (64, NSPLIT). CTA: M=128, N=256, K=4096.
// Stage (96KB x2): A_hi 16K | A_lo 16K | B_hi 32K | B_lo 32K
// ---------------------------------------------------------------------------
#define ST_SZ 98304
#define ATTN_SMEM (2 * ST_SZ)   // 196608

__global__ __launch_bounds__(256, 1) void k_gat_attn_mma()
{
    extern __shared__ char smem[];
    __shared__ float sden[256];
    const uint32_t sb = smem_u32(smem);
    const int tid = threadIdx.x;
    const int lane = tid & 31;
    const int wid = tid >> 5;

    const int row0 = blockIdx.x * 128;
    const int half = blockIdx.y;
    const int jbase = half * KHALF;

    // producer mapping: 2 threads per i-row, 32 j each
    const int r  = tid & 127;
    const int kg = tid >> 7;
    const float my_ssrc = g_s[row0 + r];
    const float* __restrict__ sdst = g_s + N_NODES;
    const char* __restrict__ hhi = (const char*)(g_hT_hi + (size_t)tid * N_NODES + jbase);
    const char* __restrict__ hlo = (const char*)(g_hT_lo + (size_t)tid * N_NODES + jbase);
    const uint32_t abase = (uint32_t)r * 128 + kg * 64;

    // consumer mapping: warp (warp_m, warp_n) owns 64x64 of the 128x256 tile
    const int warp_m = wid & 1;
    const int warp_n = wid >> 1;
    const uint32_t arow_base = (uint32_t)(warp_m * 64 + (lane & 15)) * 128;
    const int ksw = lane & 7;
    const int alsel = lane >> 4;

    float acc[4][8][4];
#pragma unroll
    for (int mt = 0; mt < 4; mt++)
#pragma unroll
        for (int nt = 0; nt < 8; nt++)
#pragma unroll
            for (int q = 0; q < 4; q++) acc[mt][nt][q] = 0.f;
    float psum = 0.f;

    // --- produce one quarter (8 j-values) of the A tile for chunk jc into stage ps
#define PROD_Q(ps_, qt_, mword_, spp_)                                            \
    {                                                                             \
        _Pragma("unroll")                                                         \
        for (int i = 0; i < 2; i++) {                                             \
            float4 sv = __ldg((spp_) + (qt_) * 2 + i);                            \
            uint32_t mb = (mword_) >> ((qt_) * 8 + i * 4);                        \
            float w0 = (mb & 1u) ? __expf(fast_mish(my_ssrc + sv.x)) : 0.f;       \
            float w1 = (mb & 2u) ? __expf(fast_mish(my_ssrc + sv.y)) : 0.f;       \
            float w2 = (mb & 4u) ? __expf(fast_mish(my_ssrc + sv.z)) : 0.f;       \
            float w3 = (mb & 8u) ? __expf(fast_mish(my_ssrc + sv.w)) : 0.f;       \
            psum += (w0 + w1) + (w2 + w3);                                        \
            uint32_t h01 = pack_bf16(w0, w1), h23 = pack_bf16(w2, w3);            \
            float r0 = w0 - __bfloat162float(__float2bfloat16(w0));               \
            float r1 = w1 - __bfloat162float(__float2bfloat16(w1));               \
            float r2 = w2 - __bfloat162float(__float2bfloat16(w2));               \
            float r3 = w3 - __bfloat162float(__float2bfloat16(w3));               \
            uint32_t l01 = pack_bf16(r0, r1), l23 = pack_bf16(r2, r3);            \
            uint32_t bo = SW128(abase + (qt_) * 16 + i * 8);                      \
            *(uint64_t*)(smem + (ps_) * ST_SZ + bo) =                             \
                (uint64_t)h01 | ((uint64_t)h23 << 32);                            \
            *(uint64_t*)(smem + (ps_) * ST_SZ + 16384 + bo) =                     \
                (uint64_t)l01 | ((uint64_t)l23 << 32);                            \
        }                                                                         \
    }

#define PROD_B(ps_, c_)                                                           \
    {                                                                             \
        const size_t go = (size_t)(c_) * (BKC * 2);                               \
        const uint32_t db = (uint32_t)tid * 128;                                  \
        const uint32_t bb = sb + (ps_) * ST_SZ + 32768;                           \
        _Pragma("unroll")                                                         \
        for (int t = 0; t < 8; t++) {                                             \
            uint32_t so = SW128(db + t * 16);                                     \
            cpa16(bb + so, hhi + go + t * 16);                                    \
            cpa16(bb + 32768 + so, hlo + go + t * 16);                            \
        }                                                                         \
        CPA_COMMIT();                                                             \
    }

    // ---- prologue: fully produce chunk 0 into stage 0 ----
    {
        PROD_B(0, 0);
        const uint32_t m0 = g_maskT[(size_t)((jbase >> 5) + kg) * N_NODES + row0 + r];
        const float4* sp0 = (const float4*)(sdst + jbase + kg * 32);
        PROD_Q(0, 0, m0, sp0); PROD_Q(0, 1, m0, sp0);
        PROD_Q(0, 2, m0, sp0); PROD_Q(0, 3, m0, sp0);
        CPA_WAIT0();
        __syncthreads();
    }

    for (int c = 0; c < NCHUNK; c++) {
        const int st = c & 1, ns = st ^ 1;
        const bool more = (c + 1 < NCHUNK);
        const uint32_t sbase = sb + st * ST_SZ;

        // issue next B tile cp.async + fetch next mask/scores early
        uint32_t mw = 0;
        const float4* sp = nullptr;
        if (more) {
            PROD_B(ns, c + 1);
            const int j1 = jbase + (c + 1) * BKC;
            mw = g_maskT[(size_t)((j1 >> 5) + kg) * N_NODES + row0 + r];
            sp = (const float4*)(sdst + j1 + kg * 32);
        }

        // interleave: consume slice ks of stage st / produce quarter ks of stage ns
#pragma unroll
        for (int ks = 0; ks < 4; ks++) {
            uint32_t Ah[4][4], Al[4][4];
            const int kcA = ks * 2 + alsel;
#pragma unroll
            for (int mt = 0; mt < 4; mt++) {
                uint32_t addr = sbase + arow_base + mt * 2048 +
                                (uint32_t)((kcA ^ ksw) << 4);
                ldsm4(Ah[mt], addr);
                ldsm4(Al[mt], addr + 16384);
            }
#pragma unroll
            for (int ng = 0; ng < 4; ng++) {
                const int g = lane >> 3;
                const int brow = warp_n * 64 + ng * 16 + (lane & 7) + ((g & 2) << 2);
                const int kcB = ks * 2 + (g & 1);
                uint32_t baddr = sbase + 32768 + (uint32_t)brow * 128 +
                                 (uint32_t)((kcB ^ ksw) << 4);
                uint32_t Bh[4], Bl[4];
                ldsm4(Bh, baddr);
                ldsm4(Bl, baddr + 32768);
#pragma unroll
                for (int mt = 0; mt < 4; mt++) {
                    mma_bf16(acc[mt][ng * 2],     Ah[mt], Bh[0], Bh[1]);
                    mma_bf16(acc[mt][ng * 2 + 1], Ah[mt], Bh[2], Bh[3]);
                    mma_bf16(acc[mt][ng * 2],     Ah[mt], Bl[0], Bl[1]);
                    mma_bf16(acc[mt][ng * 2 + 1], Ah[mt], Bl[2], Bl[3]);
                    mma_bf16(acc[mt][ng * 2],     Al[mt], Bh[0], Bh[1]);
                    mma_bf16(acc[mt][ng * 2 + 1], Al[mt], Bh[2], Bh[3]);
                }
            }
            if (more) PROD_Q(ns, ks, mw, sp);
        }

        CPA_WAIT0();
        __syncthreads();
    }

    // ---- denominators ----
    sden[tid] = psum;
    __syncthreads();
    if (tid < 128)
        g_pden[half * N_NODES + row0 + tid] = sden[tid] + sden[tid + 128];

    // ---- numerators ----
    float* base = g_pnum + (size_t)half * N_NODES * FOUT;
#pragma unroll
    for (int mt = 0; mt < 4; mt++) {
#pragma unroll
        for (int nt = 0; nt < 8; nt++) {
            int row = row0 + warp_m * 64 + mt * 16 + (lane >> 2);
            int col = warp_n * 64 + nt * 8 + (lane & 3) * 2;
            float2 v0 = {acc[mt][nt][0], acc[mt][nt][1]};
            float2 v1 = {acc[mt][nt][2], acc[mt][nt][3]};
            *(float2*)&base[(size_t)row * FOUT + col] = v0;
            *(float2*)&base[(size_t)(row + 8) * FOUT + col] = v1;
        }
    }
#undef PROD_Q
#undef PROD_B
}

// ---------------------------------------------------------------------------
// Kernel 5: combine K-split partials + final mish
// ---------------------------------------------------------------------------
__global__ __launch_bounds__(256) void k_combine(float* __restrict__ out)
{
    const int idx = blockIdx.x * 256 + threadIdx.x;
    const int row = idx >> 6;
    const float4* p0 = (const float4*)g_pnum;
    const float4* p1 = (const float4*)(g_pnum + (size_t)N_NODES * FOUT);
    float inv = __fdividef(1.f, g_pden[row] + g_pden[N_NODES + row]);
    float4 a = p0[idx], b = p1[idx];
    float4 o;
    o.x = fast_mish((a.x + b.x) * inv);
    o.y = fast_mish((a.y + b.y) * inv);
    o.z = fast_mish((a.z + b.z) * inv);
    o.w = fast_mish((a.w + b.w) * inv);
    ((float4*)out)[idx] = o;
}

// ---------------------------------------------------------------------------
extern "C" void kernel_launch(void* const* d_in, const int* in_sizes, int n_in,
                              void* d_out, int out_size)
{
    const float* x   = (const float*)d_in[0];   // [8192, 512]
    const int*   adj = (const int*)  d_in[1];   // [8192, 8192]
    const float* w   = (const float*)d_in[2];   // [512, 256]
    const float* a   = (const float*)d_in[3];   // [512, 1]
    float* out = (float*)d_out;                 // [8192, 256]

    cudaFuncSetAttribute(k_gat_attn_mma, cudaFuncAttributeMaxDynamicSharedMemorySize,
                         ATTN_SMEM);

    k_mask<<<dim3(N_NODES / 32, N_NODES / 256), 256>>>(adj);
    k_sgemm_xw<<<dim3(FOUT / 64, N_NODES / 64), 256>>>(x, w);
    k_scores<<<N_NODES / 8, 256>>>(a);
    k_hsplit<<<dim3(N_NODES / 32, FOUT / 32), 256>>>();
    k_gat_attn_mma<<<dim3(N_NODES / 128, NSPLIT), 256, ATTN_SMEM>>>();
    k_combine<<<(N_NODES * FOUT / 4) / 256, 256>>>(out);
}